// round 9
// baseline (speedup 1.0000x reference)
#include <cuda_runtime.h>
#include <cuda_fp16.h>
#include <cstdint>

#define HID 256
#define MTILE 64

// ---- smem byte offsets ----
#define OFF_A   0                 // 64 rows * 528 B (fp16 activations)
#define AROWB   528
#define OFF_WB  33792             // 2 buffers * 36864
#define WBUFSZ  36864             // 256 rows * 144 B (k=64 fp16 + 16B pad)
#define WROWB   144
#define OFF_RED 33792             // overlays WB after last GEMM: 64*3*4 floats
#define OFF_OVL 70656             // overlays WB buf1 during prologue
#define OVL_W0  0                 // 768 f32
#define OVL_CV  3072              // 256 f32
#define OVL_RGB 4096              // 192 f32
#define OFF_B1  107520
#define OFF_B2  108544
#define OFF_W3  109568            // [3][256] f32
#define OFF_B3  112640
#define SMEM_TOT 112656

// fp16 weights, transposed: [layer2][chunk4][n256][k64]
__device__ __align__(16) __half g_wb[131072];
__device__ float g_cstyle[16 * HID];

// ---------- helpers ----------
__device__ __forceinline__ uint32_t s2u(const void* p) {
    uint32_t a;
    asm("{ .reg .u64 t; cvta.to.shared.u64 t, %1; cvt.u32.u64 %0, t; }" : "=r"(a) : "l"(p));
    return a;
}
__device__ __forceinline__ void ldsm4(uint32_t* r, uint32_t addr) {
    asm volatile("ldmatrix.sync.aligned.m8n8.x4.shared.b16 {%0,%1,%2,%3}, [%4];"
                 : "=r"(r[0]), "=r"(r[1]), "=r"(r[2]), "=r"(r[3]) : "r"(addr));
}
// fp16-accumulate mma: D/C are 2 packed b32 regs (each = half2)
__device__ __forceinline__ void mma16816h(uint32_t* d, const uint32_t* a, uint32_t b0, uint32_t b1) {
    asm volatile("mma.sync.aligned.m16n8k16.row.col.f16.f16.f16.f16 "
                 "{%0,%1}, {%2,%3,%4,%5}, {%6,%7}, {%0,%1};"
                 : "+r"(d[0]), "+r"(d[1])
                 : "r"(a[0]), "r"(a[1]), "r"(a[2]), "r"(a[3]), "r"(b0), "r"(b1));
}
__device__ __forceinline__ void cpasync16(uint32_t dst, const void* src) {
    asm volatile("cp.async.cg.shared.global [%0], [%1], 16;" :: "r"(dst), "l"(src));
}
#define CP_COMMIT() asm volatile("cp.async.commit_group;" ::: "memory")
#define CP_WAIT(n)  asm volatile("cp.async.wait_group %0;" :: "n"(n) : "memory")

__device__ __forceinline__ float gelu_f(float x) {
    return 0.5f * x * (1.0f + erff(x * 0.70710678118654752f));
}
__device__ __forceinline__ uint32_t pack_h2(float lo, float hi) {
    __half2 h = __floats2half2_rn(lo, hi);
    return *(uint32_t*)&h;
}
__device__ __forceinline__ float2 unpack_h2(uint32_t v) {
    return __half22float2(*(__half2*)&v);
}

// ---------- merged pre-kernel ----------
// blocks [0, 512): weight convert/transpose; blocks [512, 512+B): style vector
__global__ void prep_all(const float* __restrict__ W1, const float* __restrict__ W2,
                         const int* __restrict__ sidx, const float* __restrict__ emb,
                         const float* __restrict__ W0, const float* __restrict__ b0) {
    if (blockIdx.x < 512) {
        int idx = blockIdx.x * 256 + threadIdx.x;     // 0..131071
        int l = idx >> 16;
        int k = (idx >> 8) & 255;
        int n = idx & 255;
        float w = (l ? W2 : W1)[k * HID + n];         // W[k][n] -> B[n][k]
        int chunk = k >> 6, kc = k & 63;
        g_wb[((size_t)(l * 4 + chunk) * 256 + n) * 64 + kc] = __float2half_rn(w);
    } else {
        int b = blockIdx.x - 512, j = threadIdx.x;
        int s = sidx[b];
        float acc = b0[j];
#pragma unroll 8
        for (int k = 0; k < 64; k++)
            acc = fmaf(emb[s * 64 + k], W0[(3 + k) * HID + j], acc);
        g_cstyle[b * HID + j] = acc;
    }
}

// ---------- main kernel ----------
__device__ __forceinline__ void prefetch_chunk(uint32_t wb, const __half* gbase, int tid) {
    const char* g = (const char*)gbase + tid * 128;   // row tid, 128B
    uint32_t d = wb + tid * WROWB;
#pragma unroll
    for (int c = 0; c < 8; c++)
        cpasync16(d + c * 16, g + c * 16);
}

struct WarpCtx {
    int mg, ng, M0, lane;
    int arow, ak16off;
    int brow, bk16off;
};

__device__ __forceinline__ void run_layer(char* sm, uint32_t sb, const __half* gbase,
                                          const __half* tail, const WarpCtx& W,
                                          uint32_t C[2][8][2], int tid) {
    for (int c = 0; c < 4; c++) {
        __syncthreads();
        const __half* gn = (c < 3) ? gbase + (size_t)(c + 1) * 16384 : tail;
        if (gn) {
            prefetch_chunk(sb + OFF_WB + ((c + 1) & 1) * WBUFSZ, gn, tid);
            CP_COMMIT();
            CP_WAIT(1);
        } else {
            CP_WAIT(0);
        }
        __syncthreads();
        const uint32_t wb = sb + OFF_WB + (c & 1) * WBUFSZ;
#pragma unroll
        for (int kk = 0; kk < 64; kk += 16) {
            const int kglob = c * 64 + kk;
            uint32_t ah[2][4];
#pragma unroll
            for (int mt = 0; mt < 2; mt++) {
                uint32_t ao = sb + OFF_A + (uint32_t)(W.M0 + mt * 16 + W.arow) * AROWB
                              + (uint32_t)kglob * 2 + W.ak16off;
                ldsm4(ah[mt], ao);
            }
#pragma unroll
            for (int ntp = 0; ntp < 4; ntp++) {
                uint32_t bo = wb + (uint32_t)(W.ng * 64 + ntp * 16 + W.brow) * WROWB
                              + (uint32_t)kk * 2 + W.bk16off;
                uint32_t bh[4];
                ldsm4(bh, bo);
#pragma unroll
                for (int mt = 0; mt < 2; mt++) {
                    mma16816h(C[mt][2 * ntp],     ah[mt], bh[0], bh[1]);
                    mma16816h(C[mt][2 * ntp + 1], ah[mt], bh[2], bh[3]);
                }
            }
        }
    }
    __syncthreads();   // all LDSM reads done before A / RED gets rewritten
}

__global__ void __launch_bounds__(256, 2) nilut_mma(
    const float* __restrict__ rgb, const float* __restrict__ W0,
    const float* __restrict__ b1, const float* __restrict__ b2,
    const float* __restrict__ W3, const float* __restrict__ b3,
    float* __restrict__ out, int HW)
{
    extern __shared__ __align__(1024) char sm[];
    const uint32_t sb = s2u(sm);
    const int tid = threadIdx.x, wid = tid >> 5, lane = tid & 31;

    WarpCtx W;
    W.lane = lane;
    W.mg = wid & 1; W.ng = wid >> 1; W.M0 = W.mg * 32;
    W.arow = lane & 15;              W.ak16off = ((lane >> 4) & 1) * 16;
    W.brow = (lane & 7) + ((lane >> 4) << 3);
    W.bk16off = ((lane >> 3) & 1) * 16;

    const int pix0 = blockIdx.x * MTILE;
    const int b = pix0 / HW, hw0 = pix0 - b * HW;

    // start weight chunk (layer1, chunk0) prefetch ASAP -> buf0
    prefetch_chunk(sb + OFF_WB, g_wb, tid);
    CP_COMMIT();

    // stage resident + overlay smalls
    float* b1s = (float*)(sm + OFF_B1);
    float* b2s = (float*)(sm + OFF_B2);
    float* w3s = (float*)(sm + OFF_W3);
    float* b3s = (float*)(sm + OFF_B3);
    float* w0s  = (float*)(sm + OFF_OVL + OVL_W0);
    float* cvec = (float*)(sm + OFF_OVL + OVL_CV);
    float* rgbs = (float*)(sm + OFF_OVL + OVL_RGB);

    b1s[tid] = b1[tid];
    b2s[tid] = b2[tid];
#pragma unroll
    for (int c = 0; c < 3; c++) w3s[c * 256 + tid] = W3[3 * tid + c];
    if (tid < 4) b3s[tid] = (tid < 3) ? b3[tid] : 0.f;
    for (int i = tid; i < 768; i += 256) w0s[i] = W0[i];
    cvec[tid] = g_cstyle[b * HID + tid];
    if (tid < 192) {
        int c = tid >> 6, px = tid & 63;
        rgbs[c * 64 + px] = rgb[(size_t)(b * 3 + c) * HW + hw0 + px];
    }
    __syncthreads();

    // ---- layer 0 prologue: A = fp16(gelu(rgb.W0[0:3] + cvec)) ----
    {
        int pq = wid & 1, quarter = wid >> 1;   // 2 pixel groups x 4 j-quarters
        int p = pq * 32 + lane;                 // 0..63
        float rr = rgbs[p], gg = rgbs[64 + p], uu = rgbs[128 + p];
        char* arow = sm + OFF_A + p * AROWB;
#pragma unroll 4
        for (int q = 0; q < 32; q++) {
            int j = quarter * 64 + 2 * q;
            float2 w0a = *(const float2*)&w0s[j];
            float2 w0b = *(const float2*)&w0s[256 + j];
            float2 w0c = *(const float2*)&w0s[512 + j];
            float2 cv  = *(const float2*)&cvec[j];
            float a0 = fmaf(rr, w0a.x, fmaf(gg, w0b.x, fmaf(uu, w0c.x, cv.x)));
            float a1 = fmaf(rr, w0a.y, fmaf(gg, w0b.y, fmaf(uu, w0c.y, cv.y)));
            *(uint32_t*)(arow + j * 2) = pack_h2(gelu_f(a0), gelu_f(a1));
        }
    }

    uint32_t C[2][8][2];
#pragma unroll
    for (int mt = 0; mt < 2; mt++)
#pragma unroll
        for (int nt = 0; nt < 8; nt++) { C[mt][nt][0] = 0u; C[mt][nt][1] = 0u; }

    // ---- layer 1 GEMM ----
    run_layer(sm, sb, g_wb, g_wb + (size_t)4 * 16384, W, C, tid);

    // ---- epilogue 1: C -> gelu -> A (fp16), zero C ----
    {
        const int r0b = W.M0 + (lane >> 2);
#pragma unroll
        for (int mt = 0; mt < 2; mt++) {
            int r0 = r0b + mt * 16, r1 = r0 + 8;
#pragma unroll
            for (int nt = 0; nt < 8; nt++) {
                int j0 = W.ng * 64 + nt * 8 + (lane & 3) * 2;
                float2 bj = *(const float2*)(sm + OFF_B1 + j0 * 4);
                float2 u0 = unpack_h2(C[mt][nt][0]);
                float2 u1 = unpack_h2(C[mt][nt][1]);
                float v0 = gelu_f(u0.x + bj.x);
                float v1 = gelu_f(u0.y + bj.y);
                float v2 = gelu_f(u1.x + bj.x);
                float v3 = gelu_f(u1.y + bj.y);
                *(uint32_t*)(sm + OFF_A + r0 * AROWB + j0 * 2) = pack_h2(v0, v1);
                *(uint32_t*)(sm + OFF_A + r1 * AROWB + j0 * 2) = pack_h2(v2, v3);
                C[mt][nt][0] = 0u; C[mt][nt][1] = 0u;
            }
        }
    }
    __syncthreads();   // A ready for layer 2

    // ---- layer 2 GEMM (chunk0 already prefetched by layer-1 tail) ----
    run_layer(sm, sb, g_wb + (size_t)4 * 16384, nullptr, W, C, tid);

    // ---- head epilogue: gelu -> dot W3 -> reduce -> sigmoid ----
    {
        float* red = (float*)(sm + OFF_RED);   // [64][3][4]
        float acc[2][2][3];
#pragma unroll
        for (int mt = 0; mt < 2; mt++)
#pragma unroll
            for (int h = 0; h < 2; h++)
                acc[mt][h][0] = acc[mt][h][1] = acc[mt][h][2] = 0.f;

#pragma unroll
        for (int mt = 0; mt < 2; mt++) {
#pragma unroll
            for (int nt = 0; nt < 8; nt++) {
                int j0 = W.ng * 64 + nt * 8 + (lane & 3) * 2;
                float2 bj = *(const float2*)(sm + OFF_B2 + j0 * 4);
                float2 wx = *(const float2*)(sm + OFF_W3 + j0 * 4);
                float2 wy = *(const float2*)(sm + OFF_W3 + 1024 + j0 * 4);
                float2 wz = *(const float2*)(sm + OFF_W3 + 2048 + j0 * 4);
                float2 u0 = unpack_h2(C[mt][nt][0]);
                float2 u1 = unpack_h2(C[mt][nt][1]);
                float v0 = gelu_f(u0.x + bj.x);
                float v1 = gelu_f(u0.y + bj.y);
                float v2 = gelu_f(u1.x + bj.x);
                float v3 = gelu_f(u1.y + bj.y);
                acc[mt][0][0] = fmaf(v0, wx.x, fmaf(v1, wx.y, acc[mt][0][0]));
                acc[mt][0][1] = fmaf(v0, wy.x, fmaf(v1, wy.y, acc[mt][0][1]));
                acc[mt][0][2] = fmaf(v0, wz.x, fmaf(v1, wz.y, acc[mt][0][2]));
                acc[mt][1][0] = fmaf(v2, wx.x, fmaf(v3, wx.y, acc[mt][1][0]));
                acc[mt][1][1] = fmaf(v2, wy.x, fmaf(v3, wy.y, acc[mt][1][1]));
                acc[mt][1][2] = fmaf(v2, wz.x, fmaf(v3, wz.y, acc[mt][1][2]));
            }
        }
#pragma unroll
        for (int mt = 0; mt < 2; mt++)
#pragma unroll
            for (int h = 0; h < 2; h++)
#pragma unroll
                for (int ch = 0; ch < 3; ch++) {
                    float v = acc[mt][h][ch];
                    v += __shfl_xor_sync(0xffffffffu, v, 1);
                    v += __shfl_xor_sync(0xffffffffu, v, 2);
                    acc[mt][h][ch] = v;
                }
        if ((lane & 3) == 0) {
#pragma unroll
            for (int mt = 0; mt < 2; mt++)
#pragma unroll
                for (int h = 0; h < 2; h++) {
                    int r = W.M0 + mt * 16 + (lane >> 2) + h * 8;
#pragma unroll
                    for (int ch = 0; ch < 3; ch++)
                        red[(r * 3 + ch) * 4 + W.ng] = acc[mt][h][ch];
                }
        }
        __syncthreads();
        if (tid < 192) {
            int ch = tid >> 6, row = tid & 63;
            const float* rr = &red[(row * 3 + ch) * 4];
            float s = rr[0] + rr[1] + rr[2] + rr[3] + b3s[ch];
            out[(size_t)(b * 3 + ch) * HW + hw0 + row] = 1.f / (1.f + expf(-s));
        }
    }
}

extern "C" void kernel_launch(void* const* d_in, const int* in_sizes, int n_in,
                              void* d_out, int out_size) {
    const float* rgb  = (const float*)d_in[0];
    const int*   sidx = (const int*)  d_in[1];
    const float* emb  = (const float*)d_in[2];
    const float* W0   = (const float*)d_in[3];
    const float* b0   = (const float*)d_in[4];
    const float* W1   = (const float*)d_in[5];
    const float* b1   = (const float*)d_in[6];
    const float* W2   = (const float*)d_in[7];
    const float* b2   = (const float*)d_in[8];
    const float* W3   = (const float*)d_in[9];
    const float* b3   = (const float*)d_in[10];
    float* out = (float*)d_out;

    int B  = in_sizes[1];
    int HW = in_sizes[0] / (3 * B);
    int N  = B * HW;

    prep_all<<<512 + B, 256>>>(W1, W2, sidx, emb, W0, b0);

    cudaFuncSetAttribute(nilut_mma, cudaFuncAttributeMaxDynamicSharedMemorySize, SMEM_TOT);
    nilut_mma<<<N / MTILE, 256, SMEM_TOT>>>(rgb, W0, b1, b2, W3, b3, out, HW);
}